// round 11
// baseline (speedup 1.0000x reference)
#include <cuda_runtime.h>
#include <cuda_bf16.h>
#include <math.h>

#define EPSV 0.0001f
#define SEQ  2304
#define KT   128           // attention key tile
#define KS_STR 20          // Ks row stride (words): 16 data + 4 pad
#define VS_STR 68          // Vs row stride (words): 64 keypairs + 4 pad
#define TILE_WORDS (KT * KS_STR + 32 * VS_STR)   // 4736 words per buffer
#define KBYTES (KT * KS_STR * 4)                 // K tile bytes: 10240
#define NTILES (SEQ / KT)                        // 18

// qkv GEMM tile geometry
#define QAW 36                     // A row stride (words)
#define QBS 136                    // B row stride (words)
#define QA_WORDS (96 * QAW)        // 3456
#define QB_WORDS (32 * QBS)        // 4352
#define QBUF (QA_WORDS + QB_WORDS) // 7808 words per buffer

// out GEMM tile geometry (64 rows x 128 cols)
#define OA_WORDS (64 * QAW)        // 2304
#define OBUF (OA_WORDS + QB_WORDS) // 6656 words per buffer

// ---------------- scratch (device globals) ------------------------------------
__device__ float    g_wqkv[768 * 256];              // normalized qkv weight (f32)
__device__ float    g_wout[256 * 256];              // normalized out weight (f32)
__device__ unsigned g_qkvh[2 * 8 * 3 * SEQ * 16];   // bf16x2 words (Q pre-scaled, K)
__device__ unsigned g_vTw[16 * 32 * (SEQ / 2)];     // V transposed: [nh][ch][s] bf16
__device__ float    g_att[2 * 256 * SEQ];

// ---------------- helpers ------------------------------------------------------
__device__ __forceinline__ float fexp2(float x) {
    float r;
    asm("ex2.approx.f32 %0, %1;" : "=f"(r) : "f"(x));
    return r;
}
__device__ __forceinline__ unsigned pack_bf(float lo, float hi) {
    unsigned r;
    asm("cvt.rn.bf16x2.f32 %0, %1, %2;" : "=r"(r) : "f"(hi), "f"(lo));
    return r;
}
__device__ __forceinline__ void mma_tf32(float c[4],
                                         unsigned a0, unsigned a1, unsigned a2, unsigned a3,
                                         unsigned b0, unsigned b1) {
    asm volatile("mma.sync.aligned.m16n8k8.row.col.f32.tf32.tf32.f32 "
                 "{%0,%1,%2,%3}, {%4,%5,%6,%7}, {%8,%9}, {%0,%1,%2,%3};"
                 : "+f"(c[0]), "+f"(c[1]), "+f"(c[2]), "+f"(c[3])
                 : "r"(a0), "r"(a1), "r"(a2), "r"(a3), "r"(b0), "r"(b1));
}
__device__ __forceinline__ void mma_bf16(float c[4],
                                         unsigned a0, unsigned a1, unsigned a2, unsigned a3,
                                         unsigned b0, unsigned b1) {
    asm volatile("mma.sync.aligned.m16n8k16.row.col.f32.bf16.bf16.f32 "
                 "{%0,%1,%2,%3}, {%4,%5,%6,%7}, {%8,%9}, {%0,%1,%2,%3};"
                 : "+f"(c[0]), "+f"(c[1]), "+f"(c[2]), "+f"(c[3])
                 : "r"(a0), "r"(a1), "r"(a2), "r"(a3), "r"(b0), "r"(b1));
}
__device__ __forceinline__ void ldsm_x4(unsigned r[4], unsigned addr) {
    asm volatile("ldmatrix.sync.aligned.m8n8.x4.shared.b16 {%0,%1,%2,%3}, [%4];"
                 : "=r"(r[0]), "=r"(r[1]), "=r"(r[2]), "=r"(r[3]) : "r"(addr));
}
__device__ __forceinline__ void cpa16(unsigned saddr, const void* g) {
    asm volatile("cp.async.cg.shared.global [%0], [%1], 16;" :: "r"(saddr), "l"(g));
}
__device__ __forceinline__ void cpa_commit() {
    asm volatile("cp.async.commit_group;");
}
__device__ __forceinline__ void cpa_wait1() {
    asm volatile("cp.async.wait_group 1;");
}

// ---------------- weight normalization (coalesced; both weights) ---------------
__global__ void norm_w_kernel(const float* __restrict__ w_qkv,
                              const float* __restrict__ w_out) {
    __shared__ float red[256];
    const int row = blockIdx.x;
    const int t = threadIdx.x;
    const float* src;
    float* dst;
    int r;
    if (row < 768) { src = w_qkv; dst = g_wqkv; r = row; }
    else           { src = w_out; dst = g_wout; r = row - 768; }
    float v = src[r * 256 + t];
    red[t] = v * v;
    __syncthreads();
    #pragma unroll
    for (int s = 128; s > 0; s >>= 1) {
        if (t < s) red[t] += red[t + s];
        __syncthreads();
    }
    float norm = EPSV + sqrtf(red[0]) * 0.0625f;
    dst[r * 256 + t] = v / (norm * 16.0f);
}

// ---------------- fused qkv GEMM + normalization (cp.async pipeline) -----------
// Block = one head's 96 channels x 128 positions. 12 warps (6m x 2n), warp m16n64.
__global__ void __launch_bounds__(384, 2) gemm_qkv_fused_kernel(
        const float* __restrict__ xall) {
    __shared__ __align__(16) unsigned qsm[2][QBUF];
    float* Cs = (float*)qsm;                       // [96][132] overlays buffers
    float* inv_s = Cs + 96 * 132;                  // 384 floats

    const int tid = threadIdx.x;
    const int lane = tid & 31;
    const int wid = tid >> 5;
    const int wm = wid % 6, wn = wid / 6;
    const int gi = lane >> 2, qi = lane & 3;
    const int h = blockIdx.y;
    const int n = blockIdx.z;
    const int rowb = h * 96;
    const int colb = blockIdx.x * 128;
    const int nh = n * 8 + h;
    const float* Wn = g_wqkv + (size_t)rowb * 256;
    const float* X = xall + (size_t)n * 256 * SEQ;

    unsigned sb[2];
    sb[0] = (unsigned)__cvta_generic_to_shared(&qsm[0][0]);
    sb[1] = (unsigned)__cvta_generic_to_shared(&qsm[1][0]);

    const int ar = tid >> 3, aq = tid & 7;         // A fill (2 rounds of 384)

    // prologue: fill buffer 0 with k0 = 0
    {
        const unsigned A = sb[0], Bb = sb[0] + QA_WORDS * 4;
        cpa16(A + ar * 144 + aq * 16, Wn + (size_t)ar * 256 + aq * 4);
        cpa16(A + (ar + 48) * 144 + aq * 16, Wn + (size_t)(ar + 48) * 256 + aq * 4);
        for (int i = tid; i < 1024; i += 384) {
            int row = i >> 5, n4 = i & 31;
            cpa16(Bb + row * 544 + n4 * 16, X + (size_t)row * SEQ + colb + n4 * 4);
        }
        cpa_commit();
    }

    float acc[8][4];
    #pragma unroll
    for (int i = 0; i < 8; i++)
        #pragma unroll
        for (int j = 0; j < 4; j++) acc[i][j] = 0.0f;

    for (int t = 0; t < 8; t++) {
        if (t + 1 < 8) {
            const int k0 = (t + 1) * 32;
            const unsigned A = sb[(t + 1) & 1], Bb = sb[(t + 1) & 1] + QA_WORDS * 4;
            cpa16(A + ar * 144 + aq * 16, Wn + (size_t)ar * 256 + k0 + aq * 4);
            cpa16(A + (ar + 48) * 144 + aq * 16,
                  Wn + (size_t)(ar + 48) * 256 + k0 + aq * 4);
            for (int i = tid; i < 1024; i += 384) {
                int row = i >> 5, n4 = i & 31;
                cpa16(Bb + row * 544 + n4 * 16,
                      X + (size_t)(k0 + row) * SEQ + colb + n4 * 4);
            }
        }
        cpa_commit();
        cpa_wait1();
        __syncthreads();

        const unsigned* As = (const unsigned*)qsm[t & 1];
        const unsigned* Bs = As + QA_WORDS;
        #pragma unroll
        for (int ks = 0; ks < 4; ks++) {
            const int mrow = wm * 16 + gi;
            unsigned fa0 = As[mrow * QAW + ks * 8 + qi];
            unsigned fa1 = As[(mrow + 8) * QAW + ks * 8 + qi];
            unsigned fa2 = As[mrow * QAW + ks * 8 + qi + 4];
            unsigned fa3 = As[(mrow + 8) * QAW + ks * 8 + qi + 4];
            #pragma unroll
            for (int nb = 0; nb < 8; nb++) {
                unsigned fb0 = Bs[(ks * 8 + qi) * QBS + wn * 64 + nb * 8 + gi];
                unsigned fb1 = Bs[(ks * 8 + qi + 4) * QBS + wn * 64 + nb * 8 + gi];
                mma_tf32(acc[nb], fa0, fa1, fa2, fa3, fb0, fb1);
            }
        }
        __syncthreads();
    }

    // ---- stage C tile [96][132] to smem ----
    {
        const int rg0 = wm * 16 + gi;
        const int rg1 = rg0 + 8;
        #pragma unroll
        for (int nb = 0; nb < 8; nb++) {
            const int col = wn * 64 + nb * 8 + 2 * qi;
            *(float2*)&Cs[rg0 * 132 + col] = make_float2(acc[nb][0], acc[nb][1]);
            *(float2*)&Cs[rg1 * 132 + col] = make_float2(acc[nb][2], acc[nb][3]);
        }
    }
    __syncthreads();

    // ---- 32-channel norms: 384 tasks (tq, s), 1 thread each ----
    {
        const int tq = tid >> 7, s = tid & 127;
        float ss = 0.0f;
        #pragma unroll
        for (int c = 0; c < 32; c++) {
            float v = Cs[(3 * c + tq) * 132 + s];
            ss += v * v;
        }
        float inv = 1.0f / (EPSV + sqrtf(ss) * 0.17677669529663687f);
        if (tq == 0) inv *= 0.25503372121867511f;   // fold 1/(sqrt(32)*ln2) into Q
        inv_s[tid] = inv;
    }
    __syncthreads();

    // ---- emit Q/K (bf16x2 words) ----
    for (int i = tid; i < 2 * 128 * 16; i += 384) {
        const int tq = i >> 11;               // 0=q, 1=k
        const int rem = i & 2047;
        const int s = rem >> 4, w = rem & 15;
        const float inv = inv_s[tq * 128 + s];
        const float lo = Cs[(6 * w + tq) * 132 + s] * inv;
        const float hi = Cs[(6 * w + 3 + tq) * 132 + s] * inv;
        g_qkvh[((size_t)(nh * 3 + tq) * SEQ + colb + s) * 16 + w] = pack_bf(lo, hi);
    }
    // ---- emit V transposed [nh][ch][s], word-packed pairs ----
    for (int i = tid; i < 32 * 64; i += 384) {
        const int c = i >> 6, s2 = i & 63;
        const int s = 2 * s2;
        const float v0 = Cs[(3 * c + 2) * 132 + s] * inv_s[256 + s];
        const float v1 = Cs[(3 * c + 2) * 132 + s + 1] * inv_s[256 + s + 1];
        g_vTw[((size_t)nh * 32 + c) * (SEQ / 2) + (colb >> 1) + s2] = pack_bf(v0, v1);
    }
}

// ---------------- out GEMM (cp.async pipeline, 64x128 tile, + residual) --------
__global__ void __launch_bounds__(256, 2) gemm_out_kernel(
        float* __restrict__ out, const float* __restrict__ xall) {
    __shared__ __align__(16) unsigned osm[2][OBUF];
    const int tid = threadIdx.x;
    const int lane = tid & 31;
    const int wid = tid >> 5;
    const int wm = wid & 3, wn = wid >> 2;
    const int gi = lane >> 2, qi = lane & 3;
    const int rowb = blockIdx.y * 64;
    const int colb = blockIdx.x * 128;
    const int n = blockIdx.z;
    const float* Wn = g_wout + (size_t)rowb * 256;
    const float* B = g_att + (size_t)n * 256 * SEQ;
    const float* X = xall + (size_t)n * 256 * SEQ;
    float* C = out + (size_t)n * 256 * SEQ;

    unsigned sb[2];
    sb[0] = (unsigned)__cvta_generic_to_shared(&osm[0][0]);
    sb[1] = (unsigned)__cvta_generic_to_shared(&osm[1][0]);

    // prologue: fill buffer 0 with k0 = 0
    {
        const unsigned A = sb[0], Bb = sb[0] + OA_WORDS * 4;
        for (int i = tid; i < 512; i += 256) {
            int row = i >> 3, q = i & 7;
            cpa16(A + row * 144 + q * 16, Wn + (size_t)row * 256 + q * 4);
        }
        for (int i = tid; i < 1024; i += 256) {
            int row = i >> 5, n4 = i & 31;
            cpa16(Bb + row * 544 + n4 * 16, B + (size_t)row * SEQ + colb + n4 * 4);
        }
        cpa_commit();
    }

    float acc[8][4];
    #pragma unroll
    for (int i = 0; i < 8; i++)
        #pragma unroll
        for (int j = 0; j < 4; j++) acc[i][j] = 0.0f;

    for (int t = 0; t < 8; t++) {
        if (t + 1 < 8) {
            const int k0 = (t + 1) * 32;
            const unsigned A = sb[(t + 1) & 1], Bb = sb[(t + 1) & 1] + OA_WORDS * 4;
            for (int i = tid; i < 512; i += 256) {
                int row = i >> 3, q = i & 7;
                cpa16(A + row * 144 + q * 16, Wn + (size_t)row * 256 + k0 + q * 4);
            }
            for (int i = tid; i < 1024; i += 256) {
                int row = i >> 5, n4 = i & 31;
                cpa16(Bb + row * 544 + n4 * 16,
                      B + (size_t)(k0 + row) * SEQ + colb + n4 * 4);
            }
        }
        cpa_commit();
        cpa_wait1();
        __syncthreads();

        const unsigned* As = (const unsigned*)osm[t & 1];
        const unsigned* Bs = As + OA_WORDS;
        #pragma unroll
        for (int ks = 0; ks < 4; ks++) {
            const int mrow = wm * 16 + gi;
            unsigned fa0 = As[mrow * QAW + ks * 8 + qi];
            unsigned fa1 = As[(mrow + 8) * QAW + ks * 8 + qi];
            unsigned fa2 = As[mrow * QAW + ks * 8 + qi + 4];
            unsigned fa3 = As[(mrow + 8) * QAW + ks * 8 + qi + 4];
            #pragma unroll
            for (int nb = 0; nb < 8; nb++) {
                unsigned fb0 = Bs[(ks * 8 + qi) * QBS + wn * 64 + nb * 8 + gi];
                unsigned fb1 = Bs[(ks * 8 + qi + 4) * QBS + wn * 64 + nb * 8 + gi];
                mma_tf32(acc[nb], fa0, fa1, fa2, fa3, fb0, fb1);
            }
        }
        __syncthreads();
    }

    const float CA = 0.9191450300180578f;   // 0.7/sqrt(0.58)
    const float CB = 0.3939192985791676f;   // 0.3/sqrt(0.58)
    const int rg0 = rowb + wm * 16 + gi;
    const int rg1 = rg0 + 8;
    #pragma unroll
    for (int nb = 0; nb < 8; nb++) {
        const int col = colb + wn * 64 + nb * 8 + 2 * qi;
        float2 x0 = *(const float2*)&X[(size_t)rg0 * SEQ + col];
        float2 x1 = *(const float2*)&X[(size_t)rg1 * SEQ + col];
        float2 r0, r1;
        r0.x = CA * x0.x + CB * acc[nb][0];
        r0.y = CA * x0.y + CB * acc[nb][1];
        r1.x = CA * x1.x + CB * acc[nb][2];
        r1.y = CA * x1.y + CB * acc[nb][3];
        *(float2*)&C[(size_t)rg0 * SEQ + col] = r0;
        *(float2*)&C[(size_t)rg1 * SEQ + col] = r1;
    }
}

// ---------------- bf16 flash attention (cp.async double buffer + ldmatrix) -----
__global__ void __launch_bounds__(256, 2) attn_kernel() {
    __shared__ __align__(16) unsigned sm[2][TILE_WORDS];

    const int nh = blockIdx.y;
    const int qbase = blockIdx.x * 128;
    const int tid = threadIdx.x;
    const int wid = tid >> 5;
    const int lane = tid & 31;
    const int gi = lane >> 2;
    const int qi = lane & 3;

    const unsigned* Qw = g_qkvh + (size_t)(nh * 3 + 0) * SEQ * 16;
    const uint4* K4 = (const uint4*)(g_qkvh + (size_t)(nh * 3 + 1) * SEQ * 16);
    const unsigned* vTw = g_vTw + (size_t)nh * 32 * (SEQ / 2);

    unsigned sb[2], ka[2], va[2];
    #pragma unroll
    for (int b = 0; b < 2; b++) {
        sb[b] = (unsigned)__cvta_generic_to_shared(&sm[b][0]);
        ka[b] = sb[b] + ((lane & 7) * KS_STR + ((lane >> 3) << 2)) * 4;
        va[b] = sb[b] + KBYTES + ((((lane >> 3) << 3) + (lane & 7)) * VS_STR) * 4;
    }
    const int fk_key = tid >> 2, fk_w4 = tid & 3;
    const int fv_ch = tid >> 4, fv_j4 = tid & 15;

    {
        cpa16(sb[0] + fk_key * 80 + fk_w4 * 16, K4 + fk_key * 4 + fk_w4);
        cpa16(sb[0] + (fk_key + 64) * 80 + fk_w4 * 16, K4 + (fk_key + 64) * 4 + fk_w4);
        cpa16(sb[0] + KBYTES + fv_ch * 272 + fv_j4 * 16,
              vTw + (size_t)fv_ch * (SEQ / 2) + fv_j4 * 4);
        cpa16(sb[0] + KBYTES + (fv_ch + 16) * 272 + fv_j4 * 16,
              vTw + (size_t)(fv_ch + 16) * (SEQ / 2) + fv_j4 * 4);
        cpa_commit();
    }

    unsigned qf[2][4];
    {
        const int r0 = qbase + wid * 16 + gi;
        const int r1 = r0 + 8;
        #pragma unroll
        for (int kk = 0; kk < 2; kk++) {
            qf[kk][0] = Qw[(size_t)r0 * 16 + kk * 8 + qi];
            qf[kk][1] = Qw[(size_t)r1 * 16 + kk * 8 + qi];
            qf[kk][2] = Qw[(size_t)r0 * 16 + kk * 8 + qi + 4];
            qf[kk][3] = Qw[(size_t)r1 * 16 + kk * 8 + qi + 4];
        }
    }

    float of[4][4];
    #pragma unroll
    for (int i = 0; i < 4; i++)
        #pragma unroll
        for (int j = 0; j < 4; j++) of[i][j] = 0.0f;
    float of4[4] = {0.f, 0.f, 0.f, 0.f};
    const unsigned onesb = (gi == 0) ? 0x3F803F80u : 0u;

    for (int t = 0; t < NTILES; t++) {
        if (t + 1 < NTILES) {
            const unsigned d = sb[(t + 1) & 1];
            const int ktn = (t + 1) * KT;
            cpa16(d + fk_key * 80 + fk_w4 * 16, K4 + (ktn + fk_key) * 4 + fk_w4);
            cpa16(d + (fk_key + 64) * 80 + fk_w4 * 16, K4 + (ktn + fk_key + 64) * 4 + fk_w4);
            cpa16(d + KBYTES + fv_ch * 272 + fv_j4 * 16,
                  vTw + (size_t)fv_ch * (SEQ / 2) + (ktn >> 1) + fv_j4 * 4);
            cpa16(d + KBYTES + (fv_ch + 16) * 272 + fv_j4 * 16,
                  vTw + (size_t)(fv_ch + 16) * (SEQ / 2) + (ktn >> 1) + fv_j4 * 4);
        }
        cpa_commit();
        cpa_wait1();
        __syncthreads();

        const unsigned kaddr = ka[t & 1];
        const unsigned vaddr = va[t & 1];
        #pragma unroll
        for (int c = 0; c < 8; c++) {
            unsigned kr0[4], kr1[4], vr0[4], vr1[4];
            ldsm_x4(kr0, kaddr + (unsigned)(c * 16 * KS_STR * 4));
            ldsm_x4(kr1, kaddr + (unsigned)((c * 16 + 8) * KS_STR * 4));
            ldsm_x4(vr0, vaddr + (unsigned)(c * 32));
            ldsm_x4(vr1, vaddr + (unsigned)(c * 32 + 16));

            float s0[4] = {0.f, 0.f, 0.f, 0.f};
            float s1[4] = {0.f, 0.f, 0.f, 0.f};
            mma_bf16(s0, qf[0][0], qf[0][1], qf[0][2], qf[0][3], kr0[0], kr0[1]);
            mma_bf16(s0, qf[1][0], qf[1][1], qf[1][2], qf[1][3], kr0[2], kr0[3]);
            mma_bf16(s1, qf[0][0], qf[0][1], qf[0][2], qf[0][3], kr1[0], kr1[1]);
            mma_bf16(s1, qf[1][0], qf[1][1], qf[1][2], qf[1][3], kr1[2], kr1[3]);

            unsigned pa0 = pack_bf(fexp2(s0[0]), fexp2(s0[1]));
            unsigned pa1 = pack_bf(fexp2(s0[2]), fexp2(s0[3]));
            unsigned pa2 = pack_bf(fexp2(s1[0]), fexp2(s1[1]));
            unsigned pa3 = pack_bf(fexp2(s1[2]), fexp2(s1[3]));
            #pragma unroll
            for (int nb = 0; nb < 4; nb++)
                mma_bf16(of[nb], pa0, pa1, pa2, pa3, vr0[nb], vr1[nb]);
            mma_bf16(of4, pa0, pa1, pa2, pa3, onesb, onesb);
        }
        __syncthreads();
    }

    const float l0 = __shfl_sync(0xFFFFFFFFu, of4[0], lane & 28);
    const float l1 = __shfl_sync(0xFFFFFFFFu, of4[2], lane & 28);
    const float il0 = 1.0f / l0;
    const float il1 = 1.0f / l1;

    float* Ob = (float*)sm;                    // [128][36]
    const int r0 = wid * 16 + gi;
    #pragma unroll
    for (int nb = 0; nb < 4; nb++) {
        Ob[r0 * 36 + nb * 8 + 2 * qi]           = of[nb][0] * il0;
        Ob[r0 * 36 + nb * 8 + 2 * qi + 1]       = of[nb][1] * il0;
        Ob[(r0 + 8) * 36 + nb * 8 + 2 * qi]     = of[nb][2] * il1;
        Ob[(r0 + 8) * 36 + nb * 8 + 2 * qi + 1] = of[nb][3] * il1;
    }
    __syncthreads();

    const int n = nh >> 3, h = nh & 7;
    float* outb = g_att + ((size_t)n * 256 + h * 32) * SEQ + qbase;
    #pragma unroll
    for (int u = 0; u < 16; u++) {
        int idx = tid + u * 256;
        int vc = idx >> 7, col = idx & 127;
        outb[(size_t)vc * SEQ + col] = Ob[col * 36 + vc];
    }
}

// ---------------- launch -------------------------------------------------------
extern "C" void kernel_launch(void* const* d_in, const int* in_sizes, int n_in,
                              void* d_out, int out_size) {
    const float* x    = (const float*)d_in[0];  // (2,256,48,48)
    const float* wqkv = (const float*)d_in[1];  // (768,256,1,1)
    const float* wout = (const float*)d_in[2];  // (256,256,1,1)
    float* out = (float*)d_out;                 // (2,256,48,48)

    norm_w_kernel<<<1024, 256>>>(wqkv, wout);
    gemm_qkv_fused_kernel<<<dim3(SEQ / 128, 8, 2), 384>>>(x);
    attn_kernel<<<dim3(SEQ / 128, 16), 256>>>();
    gemm_out_kernel<<<dim3(SEQ / 128, 4, 2), 256>>>(out, x);
}

// round 13
// speedup vs baseline: 1.0515x; 1.0515x over previous
#include <cuda_runtime.h>
#include <cuda_bf16.h>
#include <math.h>

#define EPSV 0.0001f
#define SEQ  2304
#define KT   128           // attention key tile
#define KS_STR 20          // Ks row stride (words): 16 data + 4 pad
#define VS_STR 68          // Vs row stride (words): 64 keypairs + 4 pad
#define TILE_WORDS (KT * KS_STR + 32 * VS_STR)   // 4736 words per buffer
#define KBYTES (KT * KS_STR * 4)                 // K tile bytes: 10240
#define NTILES (SEQ / KT)                        // 18

// qkv GEMM tile geometry
#define QAW 36                     // A row stride (words)
#define QBS 136                    // B row stride (words)
#define QA_WORDS (96 * QAW)        // 3456
#define QB_WORDS (32 * QBS)        // 4352
#define QBUF (QA_WORDS + QB_WORDS) // 7808 words per buffer

// out GEMM tile geometry (64 rows x 64 cols, pipelined)
#define OBS 72                     // B row stride (words)
#define OA_WORDS (64 * QAW)        // 2304
#define OB_WORDS (32 * OBS)        // 2304
#define OBUF (OA_WORDS + OB_WORDS) // 4608 words per buffer (18 KB)

// ---------------- scratch (device globals) ------------------------------------
__device__ float    g_wqkv[768 * 256];              // normalized qkv weight (f32)
__device__ float    g_wout[256 * 256];              // normalized out weight (f32)
__device__ unsigned g_qkvh[2 * 8 * 3 * SEQ * 16];   // bf16x2 words (Q pre-scaled, K)
__device__ unsigned g_vTw[16 * 32 * (SEQ / 2)];     // V transposed: [nh][ch][s] bf16
__device__ float    g_att[2 * 256 * SEQ];

// ---------------- helpers ------------------------------------------------------
__device__ __forceinline__ unsigned pack_bf(float lo, float hi) {
    unsigned r;
    asm("cvt.rn.bf16x2.f32 %0, %1, %2;" : "=r"(r) : "f"(hi), "f"(lo));
    return r;
}
__device__ __forceinline__ unsigned ex2_bf16x2(unsigned x) {
    unsigned r;
    asm("ex2.approx.ftz.bf16x2 %0, %1;" : "=r"(r) : "r"(x));
    return r;
}
__device__ __forceinline__ void mma_tf32(float c[4],
                                         unsigned a0, unsigned a1, unsigned a2, unsigned a3,
                                         unsigned b0, unsigned b1) {
    asm volatile("mma.sync.aligned.m16n8k8.row.col.f32.tf32.tf32.f32 "
                 "{%0,%1,%2,%3}, {%4,%5,%6,%7}, {%8,%9}, {%0,%1,%2,%3};"
                 : "+f"(c[0]), "+f"(c[1]), "+f"(c[2]), "+f"(c[3])
                 : "r"(a0), "r"(a1), "r"(a2), "r"(a3), "r"(b0), "r"(b1));
}
__device__ __forceinline__ void mma_bf16(float c[4],
                                         unsigned a0, unsigned a1, unsigned a2, unsigned a3,
                                         unsigned b0, unsigned b1) {
    asm volatile("mma.sync.aligned.m16n8k16.row.col.f32.bf16.bf16.f32 "
                 "{%0,%1,%2,%3}, {%4,%5,%6,%7}, {%8,%9}, {%0,%1,%2,%3};"
                 : "+f"(c[0]), "+f"(c[1]), "+f"(c[2]), "+f"(c[3])
                 : "r"(a0), "r"(a1), "r"(a2), "r"(a3), "r"(b0), "r"(b1));
}
__device__ __forceinline__ void ldsm_x4(unsigned r[4], unsigned addr) {
    asm volatile("ldmatrix.sync.aligned.m8n8.x4.shared.b16 {%0,%1,%2,%3}, [%4];"
                 : "=r"(r[0]), "=r"(r[1]), "=r"(r[2]), "=r"(r[3]) : "r"(addr));
}
__device__ __forceinline__ void cpa16(unsigned saddr, const void* g) {
    asm volatile("cp.async.cg.shared.global [%0], [%1], 16;" :: "r"(saddr), "l"(g));
}
__device__ __forceinline__ void cpa_commit() {
    asm volatile("cp.async.commit_group;");
}
__device__ __forceinline__ void cpa_wait1() {
    asm volatile("cp.async.wait_group 1;");
}

// ---------------- weight normalization (coalesced; both weights) ---------------
__global__ void norm_w_kernel(const float* __restrict__ w_qkv,
                              const float* __restrict__ w_out) {
    __shared__ float red[256];
    const int row = blockIdx.x;
    const int t = threadIdx.x;
    const float* src;
    float* dst;
    int r;
    if (row < 768) { src = w_qkv; dst = g_wqkv; r = row; }
    else           { src = w_out; dst = g_wout; r = row - 768; }
    float v = src[r * 256 + t];
    red[t] = v * v;
    __syncthreads();
    #pragma unroll
    for (int s = 128; s > 0; s >>= 1) {
        if (t < s) red[t] += red[t + s];
        __syncthreads();
    }
    float norm = EPSV + sqrtf(red[0]) * 0.0625f;
    dst[r * 256 + t] = v / (norm * 16.0f);
}

// ---------------- fused qkv GEMM + normalization (cp.async pipeline) -----------
// Block = one head's 96 channels x 128 positions. 12 warps (6m x 2n), warp m16n64.
__global__ void __launch_bounds__(384, 2) gemm_qkv_fused_kernel(
        const float* __restrict__ xall) {
    __shared__ __align__(16) unsigned qsm[2][QBUF];
    float* Cs = (float*)qsm;                       // [96][132] overlays buffers
    float* inv_s = Cs + 96 * 132;                  // 384 floats

    const int tid = threadIdx.x;
    const int lane = tid & 31;
    const int wid = tid >> 5;
    const int wm = wid % 6, wn = wid / 6;
    const int gi = lane >> 2, qi = lane & 3;
    const int h = blockIdx.y;
    const int n = blockIdx.z;
    const int rowb = h * 96;
    const int colb = blockIdx.x * 128;
    const int nh = n * 8 + h;
    const float* Wn = g_wqkv + (size_t)rowb * 256;
    const float* X = xall + (size_t)n * 256 * SEQ;

    unsigned sb[2];
    sb[0] = (unsigned)__cvta_generic_to_shared(&qsm[0][0]);
    sb[1] = (unsigned)__cvta_generic_to_shared(&qsm[1][0]);

    const int ar = tid >> 3, aq = tid & 7;         // A fill (2 rounds of 384)

    // prologue: fill buffer 0 with k0 = 0
    {
        const unsigned A = sb[0], Bb = sb[0] + QA_WORDS * 4;
        cpa16(A + ar * 144 + aq * 16, Wn + (size_t)ar * 256 + aq * 4);
        cpa16(A + (ar + 48) * 144 + aq * 16, Wn + (size_t)(ar + 48) * 256 + aq * 4);
        for (int i = tid; i < 1024; i += 384) {
            int row = i >> 5, n4 = i & 31;
            cpa16(Bb + row * 544 + n4 * 16, X + (size_t)row * SEQ + colb + n4 * 4);
        }
        cpa_commit();
    }

    float acc[8][4];
    #pragma unroll
    for (int i = 0; i < 8; i++)
        #pragma unroll
        for (int j = 0; j < 4; j++) acc[i][j] = 0.0f;

    for (int t = 0; t < 8; t++) {
        if (t + 1 < 8) {
            const int k0 = (t + 1) * 32;
            const unsigned A = sb[(t + 1) & 1], Bb = sb[(t + 1) & 1] + QA_WORDS * 4;
            cpa16(A + ar * 144 + aq * 16, Wn + (size_t)ar * 256 + k0 + aq * 4);
            cpa16(A + (ar + 48) * 144 + aq * 16,
                  Wn + (size_t)(ar + 48) * 256 + k0 + aq * 4);
            for (int i = tid; i < 1024; i += 384) {
                int row = i >> 5, n4 = i & 31;
                cpa16(Bb + row * 544 + n4 * 16,
                      X + (size_t)(k0 + row) * SEQ + colb + n4 * 4);
            }
        }
        cpa_commit();
        cpa_wait1();
        __syncthreads();

        const unsigned* As = (const unsigned*)qsm[t & 1];
        const unsigned* Bs = As + QA_WORDS;
        #pragma unroll
        for (int ks = 0; ks < 4; ks++) {
            const int mrow = wm * 16 + gi;
            unsigned fa0 = As[mrow * QAW + ks * 8 + qi];
            unsigned fa1 = As[(mrow + 8) * QAW + ks * 8 + qi];
            unsigned fa2 = As[mrow * QAW + ks * 8 + qi + 4];
            unsigned fa3 = As[(mrow + 8) * QAW + ks * 8 + qi + 4];
            #pragma unroll
            for (int nb = 0; nb < 8; nb++) {
                unsigned fb0 = Bs[(ks * 8 + qi) * QBS + wn * 64 + nb * 8 + gi];
                unsigned fb1 = Bs[(ks * 8 + qi + 4) * QBS + wn * 64 + nb * 8 + gi];
                mma_tf32(acc[nb], fa0, fa1, fa2, fa3, fb0, fb1);
            }
        }
        __syncthreads();
    }

    // ---- stage C tile [96][132] to smem ----
    {
        const int rg0 = wm * 16 + gi;
        const int rg1 = rg0 + 8;
        #pragma unroll
        for (int nb = 0; nb < 8; nb++) {
            const int col = wn * 64 + nb * 8 + 2 * qi;
            *(float2*)&Cs[rg0 * 132 + col] = make_float2(acc[nb][0], acc[nb][1]);
            *(float2*)&Cs[rg1 * 132 + col] = make_float2(acc[nb][2], acc[nb][3]);
        }
    }
    __syncthreads();

    // ---- 32-channel norms: 384 tasks (tq, s), 1 thread each ----
    {
        const int tq = tid >> 7, s = tid & 127;
        float ss = 0.0f;
        #pragma unroll
        for (int c = 0; c < 32; c++) {
            float v = Cs[(3 * c + tq) * 132 + s];
            ss += v * v;
        }
        float inv = 1.0f / (EPSV + sqrtf(ss) * 0.17677669529663687f);
        if (tq == 0) inv *= 0.25503372121867511f;   // fold 1/(sqrt(32)*ln2) into Q
        inv_s[tid] = inv;
    }
    __syncthreads();

    // ---- emit Q/K (bf16x2 words) ----
    for (int i = tid; i < 2 * 128 * 16; i += 384) {
        const int tq = i >> 11;               // 0=q, 1=k
        const int rem = i & 2047;
        const int s = rem >> 4, w = rem & 15;
        const float inv = inv_s[tq * 128 + s];
        const float lo = Cs[(6 * w + tq) * 132 + s] * inv;
        const float hi = Cs[(6 * w + 3 + tq) * 132 + s] * inv;
        g_qkvh[((size_t)(nh * 3 + tq) * SEQ + colb + s) * 16 + w] = pack_bf(lo, hi);
    }
    // ---- emit V transposed [nh][ch][s], word-packed pairs ----
    for (int i = tid; i < 32 * 64; i += 384) {
        const int c = i >> 6, s2 = i & 63;
        const int s = 2 * s2;
        const float v0 = Cs[(3 * c + 2) * 132 + s] * inv_s[256 + s];
        const float v1 = Cs[(3 * c + 2) * 132 + s + 1] * inv_s[256 + s + 1];
        g_vTw[((size_t)nh * 32 + c) * (SEQ / 2) + (colb >> 1) + s2] = pack_bf(v0, v1);
    }
}

// ---------------- out GEMM (cp.async pipeline, 64x64 tile, + residual) ---------
__global__ void __launch_bounds__(256, 2) gemm_out_kernel(
        float* __restrict__ out, const float* __restrict__ xall) {
    __shared__ __align__(16) unsigned osm[2][OBUF];
    const int tid = threadIdx.x;
    const int lane = tid & 31;
    const int wid = tid >> 5;
    const int wm = wid & 3, wn = wid >> 2;
    const int gi = lane >> 2, qi = lane & 3;
    const int rowb = blockIdx.y * 64;
    const int colb = blockIdx.x * 64;
    const int n = blockIdx.z;
    const float* Wn = g_wout + (size_t)rowb * 256;
    const float* B = g_att + (size_t)n * 256 * SEQ;
    const float* X = xall + (size_t)n * 256 * SEQ;
    float* C = out + (size_t)n * 256 * SEQ;

    unsigned sb[2];
    sb[0] = (unsigned)__cvta_generic_to_shared(&osm[0][0]);
    sb[1] = (unsigned)__cvta_generic_to_shared(&osm[1][0]);

    const int ar = tid >> 2, aq = tid & 3;     // A fill: row, float4 quad (2 each)
    const int br = tid >> 3, bq = tid & 7;     // B fill: 32 rows x 16 uint4 (2 each)

    // prologue: fill buffer 0 with k0 = 0
    {
        const unsigned A = sb[0], Bb = sb[0] + OA_WORDS * 4;
        cpa16(A + ar * 144 + aq * 16, Wn + (size_t)ar * 256 + aq * 4);
        cpa16(A + ar * 144 + 64 + aq * 16, Wn + (size_t)ar * 256 + 16 + aq * 4);
        cpa16(Bb + br * 288 + bq * 16, B + (size_t)br * SEQ + colb + bq * 4);
        cpa16(Bb + br * 288 + 128 + bq * 16,
              B + (size_t)br * SEQ + colb + 32 + bq * 4);
    }
    cpa_commit();

    float acc[4][4];
    #pragma unroll
    for (int i = 0; i < 4; i++)
        #pragma unroll
        for (int j = 0; j < 4; j++) acc[i][j] = 0.0f;

    for (int t = 0; t < 8; t++) {
        if (t + 1 < 8) {
            const int k0 = (t + 1) * 32;
            const unsigned A = sb[(t + 1) & 1], Bb = sb[(t + 1) & 1] + OA_WORDS * 4;
            cpa16(A + ar * 144 + aq * 16, Wn + (size_t)ar * 256 + k0 + aq * 4);
            cpa16(A + ar * 144 + 64 + aq * 16,
                  Wn + (size_t)ar * 256 + k0 + 16 + aq * 4);
            cpa16(Bb + br * 288 + bq * 16,
                  B + (size_t)(k0 + br) * SEQ + colb + bq * 4);
            cpa16(Bb + br * 288 + 128 + bq * 16,
                  B + (size_t)(k0 + br) * SEQ + colb + 32 + bq * 4);
        }
        cpa_commit();
        cpa_wait1();
        __syncthreads();

        const unsigned* As = (const unsigned*)osm[t & 1];
        const unsigned* Bs = As + OA_WORDS;
        #pragma unroll
        for (int ks = 0; ks < 4; ks++) {
            const int mrow = wm * 16 + gi;
            unsigned fa0 = As[mrow * QAW + ks * 8 + qi];
            unsigned fa1 = As[(mrow + 8) * QAW + ks * 8 + qi];
            unsigned fa2 = As[mrow * QAW + ks * 8 + qi + 4];
            unsigned fa3 = As[(mrow + 8) * QAW + ks * 8 + qi + 4];
            #pragma unroll
            for (int nb = 0; nb < 4; nb++) {
                unsigned fb0 = Bs[(ks * 8 + qi) * OBS + wn * 32 + nb * 8 + gi];
                unsigned fb1 = Bs[(ks * 8 + qi + 4) * OBS + wn * 32 + nb * 8 + gi];
                mma_tf32(acc[nb], fa0, fa1, fa2, fa3, fb0, fb1);
            }
        }
        __syncthreads();
    }

    const float CA = 0.9191450300180578f;   // 0.7/sqrt(0.58)
    const float CB = 0.3939192985791676f;   // 0.3/sqrt(0.58)
    const int rg0 = rowb + wm * 16 + gi;
    const int rg1 = rg0 + 8;
    #pragma unroll
    for (int nb = 0; nb < 4; nb++) {
        const int col = colb + wn * 32 + nb * 8 + 2 * qi;
        float2 x0 = *(const float2*)&X[(size_t)rg0 * SEQ + col];
        float2 x1 = *(const float2*)&X[(size_t)rg1 * SEQ + col];
        float2 r0, r1;
        r0.x = CA * x0.x + CB * acc[nb][0];
        r0.y = CA * x0.y + CB * acc[nb][1];
        r1.x = CA * x1.x + CB * acc[nb][2];
        r1.y = CA * x1.y + CB * acc[nb][3];
        *(float2*)&C[(size_t)rg0 * SEQ + col] = r0;
        *(float2*)&C[(size_t)rg1 * SEQ + col] = r1;
    }
}

// ---------------- bf16 flash attention (cp.async + ldmatrix + bf16x2 ex2) ------
__global__ void __launch_bounds__(256, 2) attn_kernel() {
    __shared__ __align__(16) unsigned sm[2][TILE_WORDS];

    const int nh = blockIdx.y;
    const int qbase = blockIdx.x * 128;
    const int tid = threadIdx.x;
    const int wid = tid >> 5;
    const int lane = tid & 31;
    const int gi = lane >> 2;
    const int qi = lane & 3;

    const unsigned* Qw = g_qkvh + (size_t)(nh * 3 + 0) * SEQ * 16;
    const uint4* K4 = (const uint4*)(g_qkvh + (size_t)(nh * 3 + 1) * SEQ * 16);
    const unsigned* vTw = g_vTw + (size_t)nh * 32 * (SEQ / 2);

    unsigned sb[2], ka[2], va[2];
    #pragma unroll
    for (int b = 0; b < 2; b++) {
        sb[b] = (unsigned)__cvta_generic_to_shared(&sm[b][0]);
        ka[b] = sb[b] + ((lane & 7) * KS_STR + ((lane >> 3) << 2)) * 4;
        va[b] = sb[b] + KBYTES + ((((lane >> 3) << 3) + (lane & 7)) * VS_STR) * 4;
    }
    const int fk_key = tid >> 2, fk_w4 = tid & 3;
    const int fv_ch = tid >> 4, fv_j4 = tid & 15;

    {
        cpa16(sb[0] + fk_key * 80 + fk_w4 * 16, K4 + fk_key * 4 + fk_w4);
        cpa16(sb[0] + (fk_key + 64) * 80 + fk_w4 * 16, K4 + (fk_key + 64) * 4 + fk_w4);
        cpa16(sb[0] + KBYTES + fv_ch * 272 + fv_j4 * 16,
              vTw + (size_t)fv_ch * (SEQ / 2) + fv_j4 * 4);
        cpa16(sb[0] + KBYTES + (fv_ch + 16) * 272 + fv_j4 * 16,
              vTw + (size_t)(fv_ch + 16) * (SEQ / 2) + fv_j4 * 4);
        cpa_commit();
    }

    unsigned qf[2][4];
    {
        const int r0 = qbase + wid * 16 + gi;
        const int r1 = r0 + 8;
        #pragma unroll
        for (int kk = 0; kk < 2; kk++) {
            qf[kk][0] = Qw[(size_t)r0 * 16 + kk * 8 + qi];
            qf[kk][1] = Qw[(size_t)r1 * 16 + kk * 8 + qi];
            qf[kk][2] = Qw[(size_t)r0 * 16 + kk * 8 + qi + 4];
            qf[kk][3] = Qw[(size_t)r1 * 16 + kk * 8 + qi + 4];
        }
    }

    float of[4][4];
    #pragma unroll
    for (int i = 0; i < 4; i++)
        #pragma unroll
        for (int j = 0; j < 4; j++) of[i][j] = 0.0f;
    float of4[4] = {0.f, 0.f, 0.f, 0.f};
    const unsigned onesb = (gi == 0) ? 0x3F803F80u : 0u;

    for (int t = 0; t < NTILES; t++) {
        if (t + 1 < NTILES) {
            const unsigned d = sb[(t + 1) & 1];
            const int ktn = (t + 1) * KT;
            cpa16(d + fk_key * 80 + fk_w4 * 16, K4 + (ktn + fk_key) * 4 + fk_w4);
            cpa16(d + (fk_key + 64) * 80 + fk_w4 * 16, K4 + (ktn + fk_key + 64) * 4 + fk_w4);
            cpa16(d + KBYTES + fv_ch * 272 + fv_j4 * 16,
                  vTw + (size_t)fv_ch * (SEQ / 2) + (ktn >> 1) + fv_j4 * 4);
            cpa16(d + KBYTES + (fv_ch + 16) * 272 + fv_j4 * 16,
                  vTw + (size_t)(fv_ch + 16) * (SEQ / 2) + (ktn >> 1) + fv_j4 * 4);
        }
        cpa_commit();
        cpa_wait1();
        __syncthreads();

        const unsigned kaddr = ka[t & 1];
        const unsigned vaddr = va[t & 1];
        #pragma unroll
        for (int c = 0; c < 8; c++) {
            unsigned kr0[4], kr1[4], vr0[4], vr1[4];
            ldsm_x4(kr0, kaddr + (unsigned)(c * 16 * KS_STR * 4));
            ldsm_x4(kr1, kaddr + (unsigned)((c * 16 + 8) * KS_STR * 4));
            ldsm_x4(vr0, vaddr + (unsigned)(c * 32));
            ldsm_x4(vr1, vaddr + (unsigned)(c * 32 + 16));

            float s0[4] = {0.f, 0.f, 0.f, 0.f};
            float s1[4] = {0.f, 0.f, 0.f, 0.f};
            mma_bf16(s0, qf[0][0], qf[0][1], qf[0][2], qf[0][3], kr0[0], kr0[1]);
            mma_bf16(s0, qf[1][0], qf[1][1], qf[1][2], qf[1][3], kr0[2], kr0[3]);
            mma_bf16(s1, qf[0][0], qf[0][1], qf[0][2], qf[0][3], kr1[0], kr1[1]);
            mma_bf16(s1, qf[1][0], qf[1][1], qf[1][2], qf[1][3], kr1[2], kr1[3]);

            // pack scores to bf16x2, then ONE MUFU op per pair
            unsigned pa0 = ex2_bf16x2(pack_bf(s0[0], s0[1]));
            unsigned pa1 = ex2_bf16x2(pack_bf(s0[2], s0[3]));
            unsigned pa2 = ex2_bf16x2(pack_bf(s1[0], s1[1]));
            unsigned pa3 = ex2_bf16x2(pack_bf(s1[2], s1[3]));
            #pragma unroll
            for (int nb = 0; nb < 4; nb++)
                mma_bf16(of[nb], pa0, pa1, pa2, pa3, vr0[nb], vr1[nb]);
            mma_bf16(of4, pa0, pa1, pa2, pa3, onesb, onesb);
        }
        __syncthreads();
    }

    const float l0 = __shfl_sync(0xFFFFFFFFu, of4[0], lane & 28);
    const float l1 = __shfl_sync(0xFFFFFFFFu, of4[2], lane & 28);
    const float il0 = 1.0f / l0;
    const float il1 = 1.0f / l1;

    float* Ob = (float*)sm;                    // [128][36]
    const int r0 = wid * 16 + gi;
    #pragma unroll
    for (int nb = 0; nb < 4; nb++) {
        Ob[r0 * 36 + nb * 8 + 2 * qi]           = of[nb][0] * il0;
        Ob[r0 * 36 + nb * 8 + 2 * qi + 1]       = of[nb][1] * il0;
        Ob[(r0 + 8) * 36 + nb * 8 + 2 * qi]     = of[nb][2] * il1;
        Ob[(r0 + 8) * 36 + nb * 8 + 2 * qi + 1] = of[nb][3] * il1;
    }
    __syncthreads();

    const int n = nh >> 3, h = nh & 7;
    float* outb = g_att + ((size_t)n * 256 + h * 32) * SEQ + qbase;
    #pragma unroll
    for (int u = 0; u < 16; u++) {
        int idx = tid + u * 256;
        int vc = idx >> 7, col = idx & 127;
        outb[(size_t)vc * SEQ + col] = Ob[col * 36 + vc];
    }
}

// ---------------- launch -------------------------------------------------------
extern "C" void kernel_launch(void* const* d_in, const int* in_sizes, int n_in,
                              void* d_out, int out_size) {
    const float* x    = (const float*)d_in[0];  // (2,256,48,48)
    const float* wqkv = (const float*)d_in[1];  // (768,256,1,1)
    const float* wout = (const float*)d_in[2];  // (256,256,1,1)
    float* out = (float*)d_out;                 // (2,256,48,48)

    norm_w_kernel<<<1024, 256>>>(wqkv, wout);
    gemm_qkv_fused_kernel<<<dim3(SEQ / 128, 8, 2), 384>>>(x);
    attn_kernel<<<dim3(SEQ / 128, 16), 256>>>();
    gemm_out_kernel<<<dim3(36, 4, 2), 256>>>(out, x);
}

// round 14
// speedup vs baseline: 1.1059x; 1.0517x over previous
#include <cuda_runtime.h>
#include <cuda_bf16.h>
#include <math.h>

#define EPSV 0.0001f
#define SEQ  2304
#define KT   128           // attention key tile
#define KS_STR 20          // Ks row stride (words): 16 data + 4 pad
#define VS_STR 68          // Vs row stride (words): 64 keypairs + 4 pad
#define TILE_WORDS (KT * KS_STR + 32 * VS_STR)   // 4736 words per buffer
#define KBYTES (KT * KS_STR * 4)                 // K tile bytes: 10240
#define NTILES (SEQ / KT)                        // 18

// qkv GEMM tile geometry
#define QAW 36                     // A row stride (words)
#define QBS 136                    // B row stride (words)
#define QA_WORDS (96 * QAW)        // 3456
#define QB_WORDS (32 * QBS)        // 4352
#define QBUF (QA_WORDS + QB_WORDS) // 7808 words per buffer

// out GEMM tile geometry (64 rows x 64 cols, BK=64)
#define OAW 68                     // A row stride (words): 64 + 4 pad
#define OBS2 72                    // B row stride (words)
#define OA2_WORDS (64 * OAW)       // 4352
#define OB2_WORDS (64 * OBS2)      // 4608
#define OBUF2 (OA2_WORDS + OB2_WORDS) // 8960 words (35.8 KB) per buffer

// ---------------- scratch (device globals) ------------------------------------
__device__ float    g_wqkv[768 * 256];              // normalized qkv weight (f32)
__device__ float    g_wout[256 * 256];              // normalized out weight (f32)
__device__ unsigned g_qkvh[2 * 8 * 3 * SEQ * 16];   // bf16x2 words (Q pre-scaled, K)
__device__ unsigned g_vTw[16 * 32 * (SEQ / 2)];     // V transposed: [nh][ch][s] bf16
__device__ float    g_att[2 * 256 * SEQ];

// ---------------- helpers ------------------------------------------------------
__device__ __forceinline__ unsigned pack_bf(float lo, float hi) {
    unsigned r;
    asm("cvt.rn.bf16x2.f32 %0, %1, %2;" : "=r"(r) : "f"(hi), "f"(lo));
    return r;
}
__device__ __forceinline__ unsigned ex2_bf16x2(unsigned x) {
    unsigned r;
    asm("ex2.approx.ftz.bf16x2 %0, %1;" : "=r"(r) : "r"(x));
    return r;
}
__device__ __forceinline__ void mma_tf32(float c[4],
                                         unsigned a0, unsigned a1, unsigned a2, unsigned a3,
                                         unsigned b0, unsigned b1) {
    asm volatile("mma.sync.aligned.m16n8k8.row.col.f32.tf32.tf32.f32 "
                 "{%0,%1,%2,%3}, {%4,%5,%6,%7}, {%8,%9}, {%0,%1,%2,%3};"
                 : "+f"(c[0]), "+f"(c[1]), "+f"(c[2]), "+f"(c[3])
                 : "r"(a0), "r"(a1), "r"(a2), "r"(a3), "r"(b0), "r"(b1));
}
__device__ __forceinline__ void mma_bf16(float c[4],
                                         unsigned a0, unsigned a1, unsigned a2, unsigned a3,
                                         unsigned b0, unsigned b1) {
    asm volatile("mma.sync.aligned.m16n8k16.row.col.f32.bf16.bf16.f32 "
                 "{%0,%1,%2,%3}, {%4,%5,%6,%7}, {%8,%9}, {%0,%1,%2,%3};"
                 : "+f"(c[0]), "+f"(c[1]), "+f"(c[2]), "+f"(c[3])
                 : "r"(a0), "r"(a1), "r"(a2), "r"(a3), "r"(b0), "r"(b1));
}
__device__ __forceinline__ void ldsm_x4(unsigned r[4], unsigned addr) {
    asm volatile("ldmatrix.sync.aligned.m8n8.x4.shared.b16 {%0,%1,%2,%3}, [%4];"
                 : "=r"(r[0]), "=r"(r[1]), "=r"(r[2]), "=r"(r[3]) : "r"(addr));
}
__device__ __forceinline__ void cpa16(unsigned saddr, const void* g) {
    asm volatile("cp.async.cg.shared.global [%0], [%1], 16;" :: "r"(saddr), "l"(g));
}
__device__ __forceinline__ void cpa_commit() {
    asm volatile("cp.async.commit_group;");
}
__device__ __forceinline__ void cpa_wait0() {
    asm volatile("cp.async.wait_group 0;");
}

// ---------------- weight normalization (coalesced; both weights) ---------------
__global__ void norm_w_kernel(const float* __restrict__ w_qkv,
                              const float* __restrict__ w_out) {
    __shared__ float red[256];
    const int row = blockIdx.x;
    const int t = threadIdx.x;
    const float* src;
    float* dst;
    int r;
    if (row < 768) { src = w_qkv; dst = g_wqkv; r = row; }
    else           { src = w_out; dst = g_wout; r = row - 768; }
    float v = src[r * 256 + t];
    red[t] = v * v;
    __syncthreads();
    #pragma unroll
    for (int s = 128; s > 0; s >>= 1) {
        if (t < s) red[t] += red[t + s];
        __syncthreads();
    }
    float norm = EPSV + sqrtf(red[0]) * 0.0625f;
    dst[r * 256 + t] = v / (norm * 16.0f);
}

// ---------------- fused qkv GEMM + normalization (cp.async, 1 bar/tile) --------
// Block = one head's 96 channels x 128 positions. 12 warps (6m x 2n), warp m16n64.
__global__ void __launch_bounds__(384, 2) gemm_qkv_fused_kernel(
        const float* __restrict__ xall) {
    __shared__ __align__(16) unsigned qsm[2][QBUF];
    float* Cs = (float*)qsm;                       // [96][132] overlays buffers
    float* inv_s = Cs + 96 * 132;                  // 384 floats

    const int tid = threadIdx.x;
    const int lane = tid & 31;
    const int wid = tid >> 5;
    const int wm = wid % 6, wn = wid / 6;
    const int gi = lane >> 2, qi = lane & 3;
    const int h = blockIdx.y;
    const int n = blockIdx.z;
    const int rowb = h * 96;
    const int colb = blockIdx.x * 128;
    const int nh = n * 8 + h;
    const float* Wn = g_wqkv + (size_t)rowb * 256;
    const float* X = xall + (size_t)n * 256 * SEQ;

    unsigned sb[2];
    sb[0] = (unsigned)__cvta_generic_to_shared(&qsm[0][0]);
    sb[1] = (unsigned)__cvta_generic_to_shared(&qsm[1][0]);

    const int ar = tid >> 3, aq = tid & 7;         // A fill (2 rounds of 384)

    // prologue: fill buffer 0 with k0 = 0
    {
        const unsigned A = sb[0], Bb = sb[0] + QA_WORDS * 4;
        cpa16(A + ar * 144 + aq * 16, Wn + (size_t)ar * 256 + aq * 4);
        cpa16(A + (ar + 48) * 144 + aq * 16, Wn + (size_t)(ar + 48) * 256 + aq * 4);
        for (int i = tid; i < 1024; i += 384) {
            int row = i >> 5, n4 = i & 31;
            cpa16(Bb + row * 544 + n4 * 16, X + (size_t)row * SEQ + colb + n4 * 4);
        }
        cpa_commit();
    }

    float acc[8][4];
    #pragma unroll
    for (int i = 0; i < 8; i++)
        #pragma unroll
        for (int j = 0; j < 4; j++) acc[i][j] = 0.0f;

    for (int t = 0; t < 8; t++) {
        cpa_wait0();
        __syncthreads();
        if (t + 1 < 8) {
            const int k0 = (t + 1) * 32;
            const unsigned A = sb[(t + 1) & 1], Bb = sb[(t + 1) & 1] + QA_WORDS * 4;
            cpa16(A + ar * 144 + aq * 16, Wn + (size_t)ar * 256 + k0 + aq * 4);
            cpa16(A + (ar + 48) * 144 + aq * 16,
                  Wn + (size_t)(ar + 48) * 256 + k0 + aq * 4);
            for (int i = tid; i < 1024; i += 384) {
                int row = i >> 5, n4 = i & 31;
                cpa16(Bb + row * 544 + n4 * 16,
                      X + (size_t)(k0 + row) * SEQ + colb + n4 * 4);
            }
            cpa_commit();
        }

        const unsigned* As = (const unsigned*)qsm[t & 1];
        const unsigned* Bs = As + QA_WORDS;
        #pragma unroll
        for (int ks = 0; ks < 4; ks++) {
            const int mrow = wm * 16 + gi;
            unsigned fa0 = As[mrow * QAW + ks * 8 + qi];
            unsigned fa1 = As[(mrow + 8) * QAW + ks * 8 + qi];
            unsigned fa2 = As[mrow * QAW + ks * 8 + qi + 4];
            unsigned fa3 = As[(mrow + 8) * QAW + ks * 8 + qi + 4];
            #pragma unroll
            for (int nb = 0; nb < 8; nb++) {
                unsigned fb0 = Bs[(ks * 8 + qi) * QBS + wn * 64 + nb * 8 + gi];
                unsigned fb1 = Bs[(ks * 8 + qi + 4) * QBS + wn * 64 + nb * 8 + gi];
                mma_tf32(acc[nb], fa0, fa1, fa2, fa3, fb0, fb1);
            }
        }
    }
    __syncthreads();    // all compute done before Cs overlays both buffers

    // ---- stage C tile [96][132] to smem ----
    {
        const int rg0 = wm * 16 + gi;
        const int rg1 = rg0 + 8;
        #pragma unroll
        for (int nb = 0; nb < 8; nb++) {
            const int col = wn * 64 + nb * 8 + 2 * qi;
            *(float2*)&Cs[rg0 * 132 + col] = make_float2(acc[nb][0], acc[nb][1]);
            *(float2*)&Cs[rg1 * 132 + col] = make_float2(acc[nb][2], acc[nb][3]);
        }
    }
    __syncthreads();

    // ---- 32-channel norms: 384 tasks (tq, s), 1 thread each ----
    {
        const int tq = tid >> 7, s = tid & 127;
        float ss = 0.0f;
        #pragma unroll
        for (int c = 0; c < 32; c++) {
            float v = Cs[(3 * c + tq) * 132 + s];
            ss += v * v;
        }
        float inv = 1.0f / (EPSV + sqrtf(ss) * 0.17677669529663687f);
        if (tq == 0) inv *= 0.25503372121867511f;   // fold 1/(sqrt(32)*ln2) into Q
        inv_s[tid] = inv;
    }
    __syncthreads();

    // ---- emit Q/K (bf16x2 words) ----
    for (int i = tid; i < 2 * 128 * 16; i += 384) {
        const int tq = i >> 11;               // 0=q, 1=k
        const int rem = i & 2047;
        const int s = rem >> 4, w = rem & 15;
        const float inv = inv_s[tq * 128 + s];
        const float lo = Cs[(6 * w + tq) * 132 + s] * inv;
        const float hi = Cs[(6 * w + 3 + tq) * 132 + s] * inv;
        g_qkvh[((size_t)(nh * 3 + tq) * SEQ + colb + s) * 16 + w] = pack_bf(lo, hi);
    }
    // ---- emit V transposed [nh][ch][s], word-packed pairs ----
    for (int i = tid; i < 32 * 64; i += 384) {
        const int c = i >> 6, s2 = i & 63;
        const int s = 2 * s2;
        const float v0 = Cs[(3 * c + 2) * 132 + s] * inv_s[256 + s];
        const float v1 = Cs[(3 * c + 2) * 132 + s + 1] * inv_s[256 + s + 1];
        g_vTw[((size_t)nh * 32 + c) * (SEQ / 2) + (colb >> 1) + s2] = pack_bf(v0, v1);
    }
}

// ---------------- out GEMM (cp.async, BK=64, 1 bar/tile, + residual) -----------
__global__ void __launch_bounds__(256, 2) gemm_out_kernel(
        float* __restrict__ out, const float* __restrict__ xall) {
    __shared__ __align__(16) unsigned osm[2][OBUF2];
    const int tid = threadIdx.x;
    const int lane = tid & 31;
    const int wid = tid >> 5;
    const int wm = wid & 3, wn = wid >> 2;
    const int gi = lane >> 2, qi = lane & 3;
    const int rowb = blockIdx.y * 64;
    const int colb = blockIdx.x * 64;
    const int n = blockIdx.z;
    const float* Wn = g_wout + (size_t)rowb * 256;
    const float* B = g_att + (size_t)n * 256 * SEQ;
    const float* X = xall + (size_t)n * 256 * SEQ;
    float* C = out + (size_t)n * 256 * SEQ;

    unsigned sb[2];
    sb[0] = (unsigned)__cvta_generic_to_shared(&osm[0][0]);
    sb[1] = (unsigned)__cvta_generic_to_shared(&osm[1][0]);

    const int fr = tid >> 2, fq = tid & 3;   // fill: row 0..63, quad base 0..3

    // prologue: fill buffer 0 with k0 = 0 (A: 64x16 quads, B: 64x16 quads)
    {
        const unsigned A = sb[0], Bb = sb[0] + OA2_WORDS * 4;
        #pragma unroll
        for (int u = 0; u < 4; u++) {
            const int q = fq + 4 * u;
            cpa16(A + fr * 272 + q * 16, Wn + (size_t)fr * 256 + q * 4);
            cpa16(Bb + fr * 288 + q * 16, B + (size_t)fr * SEQ + colb + q * 4);
        }
        cpa_commit();
    }

    float acc[4][4];
    #pragma unroll
    for (int i = 0; i < 4; i++)
        #pragma unroll
        for (int j = 0; j < 4; j++) acc[i][j] = 0.0f;

    for (int t = 0; t < 4; t++) {
        cpa_wait0();
        __syncthreads();
        if (t + 1 < 4) {
            const int k0 = (t + 1) * 64;
            const unsigned A = sb[(t + 1) & 1], Bb = sb[(t + 1) & 1] + OA2_WORDS * 4;
            #pragma unroll
            for (int u = 0; u < 4; u++) {
                const int q = fq + 4 * u;
                cpa16(A + fr * 272 + q * 16, Wn + (size_t)fr * 256 + k0 + q * 4);
                cpa16(Bb + fr * 288 + q * 16,
                      B + (size_t)(k0 + fr) * SEQ + colb + q * 4);
            }
            cpa_commit();
        }

        const unsigned* As = (const unsigned*)osm[t & 1];
        const unsigned* Bs = As + OA2_WORDS;
        #pragma unroll
        for (int ks = 0; ks < 8; ks++) {
            const int mrow = wm * 16 + gi;
            unsigned fa0 = As[mrow * OAW + ks * 8 + qi];
            unsigned fa1 = As[(mrow + 8) * OAW + ks * 8 + qi];
            unsigned fa2 = As[mrow * OAW + ks * 8 + qi + 4];
            unsigned fa3 = As[(mrow + 8) * OAW + ks * 8 + qi + 4];
            #pragma unroll
            for (int nb = 0; nb < 4; nb++) {
                unsigned fb0 = Bs[(ks * 8 + qi) * OBS2 + wn * 32 + nb * 8 + gi];
                unsigned fb1 = Bs[(ks * 8 + qi + 4) * OBS2 + wn * 32 + nb * 8 + gi];
                mma_tf32(acc[nb], fa0, fa1, fa2, fa3, fb0, fb1);
            }
        }
    }

    const float CA = 0.9191450300180578f;   // 0.7/sqrt(0.58)
    const float CB = 0.3939192985791676f;   // 0.3/sqrt(0.58)
    const int rg0 = rowb + wm * 16 + gi;
    const int rg1 = rg0 + 8;
    #pragma unroll
    for (int nb = 0; nb < 4; nb++) {
        const int col = colb + wn * 32 + nb * 8 + 2 * qi;
        float2 x0 = *(const float2*)&X[(size_t)rg0 * SEQ + col];
        float2 x1 = *(const float2*)&X[(size_t)rg1 * SEQ + col];
        float2 r0, r1;
        r0.x = CA * x0.x + CB * acc[nb][0];
        r0.y = CA * x0.y + CB * acc[nb][1];
        r1.x = CA * x1.x + CB * acc[nb][2];
        r1.y = CA * x1.y + CB * acc[nb][3];
        *(float2*)&C[(size_t)rg0 * SEQ + col] = r0;
        *(float2*)&C[(size_t)rg1 * SEQ + col] = r1;
    }
}

// ---------------- bf16 flash attention (cp.async, 1 bar/tile, bf16x2 ex2) ------
__global__ void __launch_bounds__(256, 2) attn_kernel() {
    __shared__ __align__(16) unsigned sm[2][TILE_WORDS];

    const int nh = blockIdx.y;
    const int qbase = blockIdx.x * 128;
    const int tid = threadIdx.x;
    const int wid = tid >> 5;
    const int lane = tid & 31;
    const int gi = lane >> 2;
    const int qi = lane & 3;

    const unsigned* Qw = g_qkvh + (size_t)(nh * 3 + 0) * SEQ * 16;
    const uint4* K4 = (const uint4*)(g_qkvh + (size_t)(nh * 3 + 1) * SEQ * 16);
    const unsigned* vTw = g_vTw + (size_t)nh * 32 * (SEQ / 2);

    unsigned sb[2], ka[2], va[2];
    #pragma unroll
    for (int b = 0; b < 2; b++) {
        sb[b] = (unsigned)__cvta_generic_to_shared(&sm[b][0]);
        ka[b] = sb[b] + ((lane & 7) * KS_STR + ((lane >> 3) << 2)) * 4;
        va[b] = sb[b] + KBYTES + ((((lane >> 3) << 3) + (lane & 7)) * VS_STR) * 4;
    }
    const int fk_key = tid >> 2, fk_w4 = tid & 3;
    const int fv_ch = tid >> 4, fv_j4 = tid & 15;

    {
        cpa16(sb[0] + fk_key * 80 + fk_w4 * 16, K4 + fk_key * 4 + fk_w4);
        cpa16(sb[0] + (fk_key + 64) * 80 + fk_w4 * 16, K4 + (fk_key + 64) * 4 + fk_w4);
        cpa16(sb[0] + KBYTES + fv_ch * 272 + fv_j4 * 16,
              vTw + (size_t)fv_ch * (SEQ / 2) + fv_j4 * 4);
        cpa16(sb[0] + KBYTES + (fv_ch + 16) * 272 + fv_j4 * 16,
              vTw + (size_t)(fv_ch + 16) * (SEQ / 2) + fv_j4 * 4);
        cpa_commit();
    }

    unsigned qf[2][4];
    {
        const int r0 = qbase + wid * 16 + gi;
        const int r1 = r0 + 8;
        #pragma unroll
        for (int kk = 0; kk < 2; kk++) {
            qf[kk][0] = Qw[(size_t)r0 * 16 + kk * 8 + qi];
            qf[kk][1] = Qw[(size_t)r1 * 16 + kk * 8 + qi];
            qf[kk][2] = Qw[(size_t)r0 * 16 + kk * 8 + qi + 4];
            qf[kk][3] = Qw[(size_t)r1 * 16 + kk * 8 + qi + 4];
        }
    }

    float of[4][4];
    #pragma unroll
    for (int i = 0; i < 4; i++)
        #pragma unroll
        for (int j = 0; j < 4; j++) of[i][j] = 0.0f;
    float of4[4] = {0.f, 0.f, 0.f, 0.f};
    const unsigned onesb = (gi == 0) ? 0x3F803F80u : 0u;

    for (int t = 0; t < NTILES; t++) {
        cpa_wait0();
        __syncthreads();
        if (t + 1 < NTILES) {
            const unsigned d = sb[(t + 1) & 1];
            const int ktn = (t + 1) * KT;
            cpa16(d + fk_key * 80 + fk_w4 * 16, K4 + (ktn + fk_key) * 4 + fk_w4);
            cpa16(d + (fk_key + 64) * 80 + fk_w4 * 16, K4 + (ktn + fk_key + 64) * 4 + fk_w4);
            cpa16(d + KBYTES + fv_ch * 272 + fv_j4 * 16,
                  vTw + (size_t)fv_ch * (SEQ / 2) + (ktn >> 1) + fv_j4 * 4);
            cpa16(d + KBYTES + (fv_ch + 16) * 272 + fv_j4 * 16,
                  vTw + (size_t)(fv_ch + 16) * (SEQ / 2) + (ktn >> 1) + fv_j4 * 4);
            cpa_commit();
        }

        const unsigned kaddr = ka[t & 1];
        const unsigned vaddr = va[t & 1];
        #pragma unroll
        for (int c = 0; c < 8; c++) {
            unsigned kr0[4], kr1[4], vr0[4], vr1[4];
            ldsm_x4(kr0, kaddr + (unsigned)(c * 16 * KS_STR * 4));
            ldsm_x4(kr1, kaddr + (unsigned)((c * 16 + 8) * KS_STR * 4));
            ldsm_x4(vr0, vaddr + (unsigned)(c * 32));
            ldsm_x4(vr1, vaddr + (unsigned)(c * 32 + 16));

            float s0[4] = {0.f, 0.f, 0.f, 0.f};
            float s1[4] = {0.f, 0.f, 0.f, 0.f};
            mma_bf16(s0, qf[0][0], qf[0][1], qf[0][2], qf[0][3], kr0[0], kr0[1]);
            mma_bf16(s0, qf[1][0], qf[1][1], qf[1][2], qf[1][3], kr0[2], kr0[3]);
            mma_bf16(s1, qf[0][0], qf[0][1], qf[0][2], qf[0][3], kr1[0], kr1[1]);
            mma_bf16(s1, qf[1][0], qf[1][1], qf[1][2], qf[1][3], kr1[2], kr1[3]);

            // pack scores to bf16x2, then ONE MUFU op per pair
            unsigned pa0 = ex2_bf16x2(pack_bf(s0[0], s0[1]));
            unsigned pa1 = ex2_bf16x2(pack_bf(s0[2], s0[3]));
            unsigned pa2 = ex2_bf16x2(pack_bf(s1[0], s1[1]));
            unsigned pa3 = ex2_bf16x2(pack_bf(s1[2], s1[3]));
            #pragma unroll
            for (int nb = 0; nb < 4; nb++)
                mma_bf16(of[nb], pa0, pa1, pa2, pa3, vr0[nb], vr1[nb]);
            mma_bf16(of4, pa0, pa1, pa2, pa3, onesb, onesb);
        }
    }

    const float l0 = __shfl_sync(0xFFFFFFFFu, of4[0], lane & 28);
    const float l1 = __shfl_sync(0xFFFFFFFFu, of4[2], lane & 28);
    const float il0 = 1.0f / l0;
    const float il1 = 1.0f / l1;

    // stage O through smem buffer 0 (last tile read buffer 1; all warps past
    // the final top-barrier, so no one still reads buffer 0)
    float* Ob = (float*)sm;                    // [128][36]
    const int r0 = wid * 16 + gi;
    #pragma unroll
    for (int nb = 0; nb < 4; nb++) {
        Ob[r0 * 36 + nb * 8 + 2 * qi]           = of[nb][0] * il0;
        Ob[r0 * 36 + nb * 8 + 2 * qi + 1]       = of[nb][1] * il0;
        Ob[(r0 + 8) * 36 + nb * 8 + 2 * qi]     = of[nb][2] * il1;
        Ob[(r0 + 8) * 36 + nb * 8 + 2 * qi + 1] = of[nb][3] * il1;
    }
    __syncthreads();

    const int n = nh >> 3, h = nh & 7;
    float* outb = g_att + ((size_t)n * 256 + h * 32) * SEQ + qbase;
    #pragma unroll
    for (int u = 0; u < 16; u++) {
        int idx = tid + u * 256;
        int vc = idx >> 7, col = idx & 127;
        outb[(size_t)vc * SEQ + col] = Ob[col * 36 + vc];
    }
}

// ---------------- launch -------------------------------------------------------
extern "C" void kernel_launch(void* const* d_in, const int* in_sizes, int n_in,
                              void* d_out, int out_size) {
    const float* x    = (const float*)d_in[0];  // (2,256,48,48)
    const float* wqkv = (const float*)d_in[1];  // (768,256,1,1)
    const float* wout = (const float*)d_in[2];  // (256,256,1,1)
    float* out = (float*)d_out;                 // (2,256,48,48)

    norm_w_kernel<<<1024, 256>>>(wqkv, wout);
    gemm_qkv_fused_kernel<<<dim3(SEQ / 128, 8, 2), 384>>>(x);
    attn_kernel<<<dim3(SEQ / 128, 16), 256>>>();
    gemm_out_kernel<<<dim3(36, 4, 2), 256>>>(out, x);
}